// round 1
// baseline (speedup 1.0000x reference)
#include <cuda_runtime.h>
#include <cstdint>

// GPUBatchProcessor: per-batch 4x4 homogeneous transform of positions +
// rotation+renormalization of normals. batch_indices is unused by the output.
//
// Layout: vertices are (B, N, 6) float32 = 24 B/vertex. Two vertices = 48 B =
// 3 float4, so each thread handles a vertex PAIR with 3x LDG.128 / 3x STG.128.

#define TPB 256

__global__ void __launch_bounds__(TPB)
xform_pair_kernel(const float4* __restrict__ vin,
                  const float*  __restrict__ xforms,   // (B,4,4) row-major
                  float4*       __restrict__ vout,
                  int pairs_per_batch,
                  int total_pairs,
                  int n_batches)
{
    __shared__ float sM[8 * 16];   // up to 8 matrices; n_batches*16 actually used
    int nm = n_batches * 16;
    if (threadIdx.x < nm) sM[threadIdx.x] = xforms[threadIdx.x];
    __syncthreads();

    int idx = blockIdx.x * TPB + threadIdx.x;
    if (idx >= total_pairs) return;

    int b = idx / pairs_per_batch;
    const float* m = &sM[b * 16];
    // matrix registers (broadcast LDS)
    const float m00 = m[0],  m01 = m[1],  m02 = m[2],  m03 = m[3];
    const float m10 = m[4],  m11 = m[5],  m12 = m[6],  m13 = m[7];
    const float m20 = m[8],  m21 = m[9],  m22 = m[10], m23 = m[11];
    const float m30 = m[12], m31 = m[13], m32 = m[14], m33 = m[15];

    size_t base = (size_t)idx * 3;
    float4 A = vin[base + 0];
    float4 Bv = vin[base + 1];
    float4 C = vin[base + 2];

    // vertex 0: pos=(A.x,A.y,A.z) nrm=(A.w,Bv.x,Bv.y)
    // vertex 1: pos=(Bv.z,Bv.w,C.x) nrm=(C.y,C.z,C.w)
    float o[12];

    #pragma unroll
    for (int v = 0; v < 2; ++v) {
        float x, y, z, nx, ny, nz;
        if (v == 0) { x = A.x; y = A.y; z = A.z; nx = A.w; ny = Bv.x; nz = Bv.y; }
        else        { x = Bv.z; y = Bv.w; z = C.x; nx = C.y; ny = C.z; nz = C.w; }

        // homogeneous transform; bottom row is [0,0,0,1] in this dataset but
        // compute generally (cheap; kernel is DRAM-bound)
        float tw = fmaf(m30, x, fmaf(m31, y, fmaf(m32, z, m33)));
        float iw = 1.0f / tw;
        float px = fmaf(m00, x, fmaf(m01, y, fmaf(m02, z, m03))) * iw;
        float py = fmaf(m10, x, fmaf(m11, y, fmaf(m12, z, m13))) * iw;
        float pz = fmaf(m20, x, fmaf(m21, y, fmaf(m22, z, m23))) * iw;

        // normal: R * n, then normalize with 1e-8 floor
        float tx = fmaf(m00, nx, fmaf(m01, ny, m02 * nz));
        float ty = fmaf(m10, nx, fmaf(m11, ny, m12 * nz));
        float tz = fmaf(m20, nx, fmaf(m21, ny, m22 * nz));
        float d  = fmaf(tx, tx, fmaf(ty, ty, tz * tz));
        float l  = fmaxf(sqrtf(d), 1e-8f);
        float il = 1.0f / l;

        o[v * 6 + 0] = px; o[v * 6 + 1] = py; o[v * 6 + 2] = pz;
        o[v * 6 + 3] = tx * il; o[v * 6 + 4] = ty * il; o[v * 6 + 5] = tz * il;
    }

    vout[base + 0] = make_float4(o[0], o[1], o[2],  o[3]);
    vout[base + 1] = make_float4(o[4], o[5], o[6],  o[7]);
    vout[base + 2] = make_float4(o[8], o[9], o[10], o[11]);
}

extern "C" void kernel_launch(void* const* d_in, const int* in_sizes, int n_in,
                              void* d_out, int out_size)
{
    const float4* vin    = (const float4*)d_in[0];     // batch_vertices (B,N,6)
    // d_in[1] = batch_indices — unused by the output
    const float*  xforms = (const float*)d_in[2];      // batch_transforms (B,4,4)

    int n_verts   = in_sizes[0] / 6;        // B*N
    int n_batches = in_sizes[2] / 16;       // B
    int N         = n_verts / n_batches;    // vertices per batch
    int pairs_per_batch = N / 2;            // N is even (1e6)
    int total_pairs     = n_verts / 2;

    int grid = (total_pairs + TPB - 1) / TPB;
    xform_pair_kernel<<<grid, TPB>>>(vin, xforms, (float4*)d_out,
                                     pairs_per_batch, total_pairs, n_batches);
}

// round 2
// speedup vs baseline: 1.0043x; 1.0043x over previous
#include <cuda_runtime.h>
#include <cstdint>

// GPUBatchProcessor: per-batch 4x4 homogeneous transform of positions +
// rotation+renormalization of normals. batch_indices is unused by the output.
//
// v2: 2D grid (y=batch, kills the integer div), 2 vertex-pairs per thread
// block-strided (6 independent coalesced LDG.128 front-batched -> higher MLP),
// streaming cache hints (data is touched exactly once).

#define TPB 256

__global__ void __launch_bounds__(TPB)
xform_pair2_kernel(const float4* __restrict__ vin,
                   const float*  __restrict__ xforms,   // (B,4,4) row-major
                   float4*       __restrict__ vout,
                   int pairs_per_batch)
{
    __shared__ float sM[16];
    if (threadIdx.x < 16) sM[threadIdx.x] = xforms[blockIdx.y * 16 + threadIdx.x];
    __syncthreads();

    const float m00 = sM[0],  m01 = sM[1],  m02 = sM[2],  m03 = sM[3];
    const float m10 = sM[4],  m11 = sM[5],  m12 = sM[6],  m13 = sM[7];
    const float m20 = sM[8],  m21 = sM[9],  m22 = sM[10], m23 = sM[11];
    const float m30 = sM[12], m31 = sM[13], m32 = sM[14], m33 = sM[15];

    const size_t batch_base = (size_t)blockIdx.y * pairs_per_batch * 3;

    int p0 = blockIdx.x * (2 * TPB) + threadIdx.x;   // first pair
    int p1 = p0 + TPB;                                // second pair (block-strided)
    bool v0 = p0 < pairs_per_batch;
    bool v1 = p1 < pairs_per_batch;

    size_t base0 = batch_base + (size_t)p0 * 3;
    size_t base1 = batch_base + (size_t)p1 * 3;

    // Front-batched streaming loads (up to 6 independent LDG.128)
    float4 A0, B0, C0, A1, B1, C1;
    if (v0) {
        A0 = __ldcs(&vin[base0 + 0]);
        B0 = __ldcs(&vin[base0 + 1]);
        C0 = __ldcs(&vin[base0 + 2]);
    }
    if (v1) {
        A1 = __ldcs(&vin[base1 + 0]);
        B1 = __ldcs(&vin[base1 + 1]);
        C1 = __ldcs(&vin[base1 + 2]);
    }

    #pragma unroll
    for (int g = 0; g < 2; ++g) {
        bool valid = (g == 0) ? v0 : v1;
        if (!valid) continue;
        float4 A = (g == 0) ? A0 : A1;
        float4 Bv = (g == 0) ? B0 : B1;
        float4 C = (g == 0) ? C0 : C1;
        size_t base = (g == 0) ? base0 : base1;

        float o[12];
        #pragma unroll
        for (int v = 0; v < 2; ++v) {
            float x, y, z, nx, ny, nz;
            if (v == 0) { x = A.x; y = A.y; z = A.z; nx = A.w; ny = Bv.x; nz = Bv.y; }
            else        { x = Bv.z; y = Bv.w; z = C.x; nx = C.y; ny = C.z; nz = C.w; }

            float tw = fmaf(m30, x, fmaf(m31, y, fmaf(m32, z, m33)));
            float iw = 1.0f / tw;
            float px = fmaf(m00, x, fmaf(m01, y, fmaf(m02, z, m03))) * iw;
            float py = fmaf(m10, x, fmaf(m11, y, fmaf(m12, z, m13))) * iw;
            float pz = fmaf(m20, x, fmaf(m21, y, fmaf(m22, z, m23))) * iw;

            float tx = fmaf(m00, nx, fmaf(m01, ny, m02 * nz));
            float ty = fmaf(m10, nx, fmaf(m11, ny, m12 * nz));
            float tz = fmaf(m20, nx, fmaf(m21, ny, m22 * nz));
            float d  = fmaf(tx, tx, fmaf(ty, ty, tz * tz));
            float l  = fmaxf(sqrtf(d), 1e-8f);
            float il = 1.0f / l;

            o[v * 6 + 0] = px;      o[v * 6 + 1] = py;      o[v * 6 + 2] = pz;
            o[v * 6 + 3] = tx * il; o[v * 6 + 4] = ty * il; o[v * 6 + 5] = tz * il;
        }

        __stcs(&vout[base + 0], make_float4(o[0], o[1], o[2],  o[3]));
        __stcs(&vout[base + 1], make_float4(o[4], o[5], o[6],  o[7]));
        __stcs(&vout[base + 2], make_float4(o[8], o[9], o[10], o[11]));
    }
}

extern "C" void kernel_launch(void* const* d_in, const int* in_sizes, int n_in,
                              void* d_out, int out_size)
{
    const float4* vin    = (const float4*)d_in[0];     // batch_vertices (B,N,6)
    // d_in[1] = batch_indices — unused by the output
    const float*  xforms = (const float*)d_in[2];      // batch_transforms (B,4,4)

    int n_verts   = in_sizes[0] / 6;        // B*N
    int n_batches = in_sizes[2] / 16;       // B
    int N         = n_verts / n_batches;    // vertices per batch
    int pairs_per_batch = N / 2;            // N even (1e6)

    dim3 grid((pairs_per_batch + 2 * TPB - 1) / (2 * TPB), n_batches);
    xform_pair2_kernel<<<grid, TPB>>>(vin, xforms, (float4*)d_out, pairs_per_batch);
}